// round 12
// baseline (speedup 1.0000x reference)
#include <cuda_runtime.h>
#include <cstdint>
#include <cstddef>

#define D 128
#define MAXN 100000
#define MAXE 1600000
#define BM 64
#define RSTR 68          // float stride: row-QUADS 16B-aligned for LDS.128
#define SCHUNK 1024
#define NBLK_SCAN 98

typedef unsigned long long u64;

// ---------------------------------------------------------------------------
// Device scratch (static; allocation-guard-safe). Zero at load; g_cnt
// re-zeroed by histscan each launch; g_bar monotonic.
// ---------------------------------------------------------------------------
__device__ float g_agg[(size_t)MAXN * D];
__device__ u64   g_edges[MAXE];
__device__ int   g_cnt[MAXN];
__device__ int   g_row[MAXN + 1];
__device__ int   g_cur[MAXN];
__device__ int   g_look[NBLK_SCAN];
__device__ unsigned g_bar;

// ---------------------------------------------------------------------------
// f32x2 helpers
// ---------------------------------------------------------------------------
__device__ __forceinline__ u64 dup2(float f) {
    u64 r; unsigned u = __float_as_uint(f);
    asm("mov.b64 %0, {%1, %1};" : "=l"(r) : "r"(u));
    return r;
}
__device__ __forceinline__ void ffma2(u64& d, u64 a, u64 b) {
    asm("fma.rn.f32x2 %0, %1, %2, %0;" : "+l"(d) : "l"(a), "l"(b));
}
__device__ __forceinline__ u64 add2(u64 a, u64 b) {
    u64 r;
    asm("add.rn.f32x2 %0, %1, %2;" : "=l"(r) : "l"(a), "l"(b));
    return r;
}

__device__ __forceinline__ bool block_sniff64(const int* p, int* s_flag) {
    if (threadIdx.x == 0) {
        unsigned o = 0;
        #pragma unroll
        for (int j = 0; j < 16; j++) o |= (unsigned)p[2 * j + 1];
        *s_flag = (o == 0u) ? 1 : 0;
    }
    __syncthreads();
    return *s_flag != 0;
}

__device__ __forceinline__ void grid_barrier(int nb) {
    __syncthreads();
    if (threadIdx.x == 0) {
        __threadfence();
        unsigned my = atomicAdd(&g_bar, 1u);
        unsigned target = (my / nb + 1u) * (unsigned)nb;
        unsigned cur;
        do {
            asm volatile("ld.acquire.gpu.global.u32 %0, [%1];"
                         : "=r"(cur) : "l"(&g_bar) : "memory");
        } while (cur < target);
    }
    __syncthreads();
}

// ---------------------------------------------------------------------------
// Launch 1: histogram + scan (98 co-resident blocks, 2 grid barriers)
// ---------------------------------------------------------------------------
__global__ void __launch_bounds__(256) histscan_kernel(const int* __restrict__ dst_raw,
                                                       int n, int E) {
    __shared__ int s_is64;
    __shared__ int wsum[8];
    __shared__ int s_red[256];
    __shared__ int s_prefix;

    const int tid  = threadIdx.x;
    const int lane = tid & 31;
    const int wid  = tid >> 5;
    const int b    = blockIdx.x;
    const int nb   = gridDim.x;

    const bool is64 = block_sniff64(dst_raw, &s_is64);
    if (is64) {
        const long long* d64 = (const long long*)dst_raw;
        for (int e = b * 256 + tid; e < E; e += nb * 256)
            atomicAdd(&g_cnt[(int)d64[e]], 1);
    } else {
        for (int e = b * 256 + tid; e < E; e += nb * 256)
            atomicAdd(&g_cnt[dst_raw[e]], 1);
    }
    grid_barrier(nb);

    const int base = b * SCHUNK + tid * 4;
    int v[4];
    #pragma unroll
    for (int j = 0; j < 4; j++)
        v[j] = (base + j < n) ? g_cnt[base + j] : 0;
    int s = v[0] + v[1] + v[2] + v[3];

    int inc = s;
    #pragma unroll
    for (int off = 1; off < 32; off <<= 1) {
        int t = __shfl_up_sync(0xffffffffu, inc, off);
        if (lane >= off) inc += t;
    }
    if (lane == 31) wsum[wid] = inc;
    __syncthreads();
    if (wid == 0) {
        int wv = (lane < 8) ? wsum[lane] : 0;
        #pragma unroll
        for (int off = 1; off < 8; off <<= 1) {
            int t = __shfl_up_sync(0xffffffffu, wv, off);
            if (lane >= off) wv += t;
        }
        if (lane < 8) wsum[lane] = wv;
    }
    __syncthreads();
    if (tid == 0) g_look[b] = wsum[7];
    grid_barrier(nb);

    s_red[tid] = (tid < b) ? g_look[tid] : 0;
    __syncthreads();
    for (int off = 128; off > 0; off >>= 1) {
        if (tid < off) s_red[tid] += s_red[tid + off];
        __syncthreads();
    }
    if (tid == 0) s_prefix = s_red[0];
    __syncthreads();

    int excl = inc - s + (wid > 0 ? wsum[wid - 1] : 0) + s_prefix;
    #pragma unroll
    for (int j = 0; j < 4; j++) {
        int idx = base + j;
        if (idx <= n) {
            g_row[idx] = excl;
            if (idx < n) { g_cur[idx] = excl; g_cnt[idx] = 0; }
        }
        excl += v[j];
    }
}

// ---------------------------------------------------------------------------
// Launch 2: scatter packed (w,src) into CSR order
// ---------------------------------------------------------------------------
__global__ void __launch_bounds__(256) scatter_kernel(const int* __restrict__ src_raw,
                                                      const int* __restrict__ dst_raw,
                                                      const float* __restrict__ w, int E) {
    __shared__ int s_is64;
    const bool is64 = block_sniff64(dst_raw, &s_is64);
    int t = blockIdx.x * blockDim.x + threadIdx.x;
    int e = t * 2;
    if (e >= E) return;
    int cnt = min(2, E - e);
    #pragma unroll
    for (int j = 0; j < 2; j++) {
        if (j >= cnt) break;
        int s, d;
        if (is64) {
            s = (int)((const long long*)src_raw)[e + j];
            d = (int)((const long long*)dst_raw)[e + j];
        } else {
            s = src_raw[e + j];
            d = dst_raw[e + j];
        }
        float ww = w[e + j];
        int pos = atomicAdd(&g_cur[d], 1);
        g_edges[pos] = ((u64)__float_as_uint(ww) << 32) | (unsigned)s;
    }
}

// ---------------------------------------------------------------------------
// Launch 3: aggregation (unchanged — known 81 us)
// ---------------------------------------------------------------------------
__global__ void __launch_bounds__(256) agg_kernel(const float* __restrict__ x, int n) {
    const int warp = (blockIdx.x * blockDim.x + threadIdx.x) >> 5;
    if (warp >= n) return;
    const int lane = threadIdx.x & 31;

    const int beg = g_row[warp];
    const int end = g_row[warp + 1];
    const float4* x4 = (const float4*)x;

    float4 a0 = make_float4(0.f, 0.f, 0.f, 0.f);
    float4 a1 = make_float4(0.f, 0.f, 0.f, 0.f);
    float4 a2 = make_float4(0.f, 0.f, 0.f, 0.f);
    float4 a3 = make_float4(0.f, 0.f, 0.f, 0.f);

    int i = beg;
    for (; i + 3 < end; i += 4) {
        u64 e0 = g_edges[i];
        u64 e1 = g_edges[i + 1];
        u64 e2 = g_edges[i + 2];
        u64 e3 = g_edges[i + 3];
        float4 v0 = __ldg(&x4[(size_t)(unsigned)e0 * (D / 4) + lane]);
        float4 v1 = __ldg(&x4[(size_t)(unsigned)e1 * (D / 4) + lane]);
        float4 v2 = __ldg(&x4[(size_t)(unsigned)e2 * (D / 4) + lane]);
        float4 v3 = __ldg(&x4[(size_t)(unsigned)e3 * (D / 4) + lane]);
        float w0 = __uint_as_float((unsigned)(e0 >> 32));
        float w1 = __uint_as_float((unsigned)(e1 >> 32));
        float w2 = __uint_as_float((unsigned)(e2 >> 32));
        float w3 = __uint_as_float((unsigned)(e3 >> 32));
        a0.x += w0 * v0.x; a0.y += w0 * v0.y; a0.z += w0 * v0.z; a0.w += w0 * v0.w;
        a1.x += w1 * v1.x; a1.y += w1 * v1.y; a1.z += w1 * v1.z; a1.w += w1 * v1.w;
        a2.x += w2 * v2.x; a2.y += w2 * v2.y; a2.z += w2 * v2.z; a2.w += w2 * v2.w;
        a3.x += w3 * v3.x; a3.y += w3 * v3.y; a3.z += w3 * v3.z; a3.w += w3 * v3.w;
    }
    for (; i < end; i++) {
        u64 e0 = g_edges[i];
        float w0 = __uint_as_float((unsigned)(e0 >> 32));
        float4 v0 = __ldg(&x4[(size_t)(unsigned)e0 * (D / 4) + lane]);
        a0.x += w0 * v0.x; a0.y += w0 * v0.y; a0.z += w0 * v0.z; a0.w += w0 * v0.w;
    }
    float4 r;
    r.x = (a0.x + a1.x) + (a2.x + a3.x);
    r.y = (a0.y + a1.y) + (a2.y + a3.y);
    r.z = (a0.z + a1.z) + (a2.z + a3.z);
    r.w = (a0.w + a1.w) + (a2.w + a3.w);
    ((float4*)g_agg)[(size_t)warp * (D / 4) + lane] = r;
}

// ---------------------------------------------------------------------------
// Launch 4 (PROFILED SLOT): dual GEMM, ALL-SMEM operands.
//   smem: Wn[128x128], Ws[128x128], A-tile[128][RSTR], X-tile[128][RSTR]
//   thread = 4 rows x 8 cols (16 u64 accs). Lane map: c0=(l&15)*8 cols,
//   rowquad r0 = w*8 + (l>>4)*4. Weight LDS.128s carry distinct bytes per
//   half-warp (2-way broadcast) -> no L1-return blowup. A/X via one aligned
//   LDS.128 row-quad each.
// ---------------------------------------------------------------------------
__global__ void __launch_bounds__(256, 1) dual_gemm_kernel(
    const float* __restrict__ x,
    const float* __restrict__ Wn,
    const float* __restrict__ Ws,
    const float* __restrict__ bias,
    float* __restrict__ out, int n)
{
    extern __shared__ float sm[];
    float* s_wn = sm;                          // 128*128
    float* s_ws = sm + 128 * 128;              // 128*128
    float* s_a  = sm + 2 * 128 * 128;          // [128][RSTR]
    float* s_x  = s_a + 128 * RSTR;

    const int tid = threadIdx.x;
    const int row0 = blockIdx.x * BM;

    // fill weights (L2-hot across blocks)
    {
        const float4* wn4 = (const float4*)Wn;
        const float4* ws4 = (const float4*)Ws;
        float4* swn4 = (float4*)s_wn;
        float4* sws4 = (float4*)s_ws;
        for (int i = tid; i < (D * D) / 4; i += 256) {
            swn4[i] = __ldg(wn4 + i);
            sws4[i] = __ldg(ws4 + i);
        }
    }
    // fill A/X tiles in [k][row] layout
    for (int idx = tid; idx < BM * D; idx += 256) {
        int r = idx >> 7;
        int k = idx & 127;
        int gr = row0 + r;
        float av = 0.f, xv = 0.f;
        if (gr < n) {
            av = g_agg[(size_t)gr * D + k];
            xv = x[(size_t)gr * D + k];
        }
        s_a[k * RSTR + r] = av;
        s_x[k * RSTR + r] = xv;
    }
    __syncthreads();

    const int wid  = tid >> 5;
    const int lane = tid & 31;
    const int c0 = (lane & 15) * 8;            // 8 cols per thread
    const int r0 = wid * 8 + (lane >> 4) * 4;  // 4 rows per thread

    u64 acc[4][4];                             // [row][colpair]
    #pragma unroll
    for (int r = 0; r < 4; r++)
        #pragma unroll
        for (int c = 0; c < 4; c++) acc[r][c] = 0ull;

    #pragma unroll 2
    for (int k = 0; k < 128; k++) {
        float4 av = *(const float4*)(s_a + k * RSTR + r0);   // rows r0..r0+3
        float4 xv = *(const float4*)(s_x + k * RSTR + r0);
        u64 A[4] = {dup2(av.x), dup2(av.y), dup2(av.z), dup2(av.w)};
        u64 X[4] = {dup2(xv.x), dup2(xv.y), dup2(xv.z), dup2(xv.w)};

        const ulonglong2* pn = (const ulonglong2*)(s_wn + k * D + c0);
        const ulonglong2* ps = (const ulonglong2*)(s_ws + k * D + c0);
        ulonglong2 n01 = pn[0];    // colpairs 0,1
        ulonglong2 n23 = pn[1];    // colpairs 2,3
        ulonglong2 t01 = ps[0];
        ulonglong2 t23 = ps[1];

        #pragma unroll
        for (int r = 0; r < 4; r++) {
            ffma2(acc[r][0], A[r], n01.x); ffma2(acc[r][0], X[r], t01.x);
            ffma2(acc[r][1], A[r], n01.y); ffma2(acc[r][1], X[r], t01.y);
            ffma2(acc[r][2], A[r], n23.x); ffma2(acc[r][2], X[r], t23.x);
            ffma2(acc[r][3], A[r], n23.y); ffma2(acc[r][3], X[r], t23.y);
        }
    }

    u64 b[4];
    #pragma unroll
    for (int c = 0; c < 4; c++) b[c] = *(const u64*)(bias + c0 + 2 * c);

    #pragma unroll
    for (int r = 0; r < 4; r++) {
        int row = row0 + r0 + r;
        if (row >= n) continue;
        float* op = out + (size_t)row * D + c0;
        ulonglong2 st0, st1;
        st0.x = add2(acc[r][0], b[0]);
        st0.y = add2(acc[r][1], b[1]);
        st1.x = add2(acc[r][2], b[2]);
        st1.y = add2(acc[r][3], b[3]);
        *(ulonglong2*)(op) = st0;
        *(ulonglong2*)(op + 4) = st1;
    }
}

// ---------------------------------------------------------------------------
// launch: histscan(1) scatter(2) agg(3) dual_gemm(4 = profiled slot)
// ---------------------------------------------------------------------------
extern "C" void kernel_launch(void* const* d_in, const int* in_sizes, int n_in,
                              void* d_out, int out_size) {
    const float* x    = (const float*)d_in[0];
    const int*   src  = (const int*)d_in[1];
    const int*   dst  = (const int*)d_in[2];
    const float* w    = (const float*)d_in[3];
    const float* Wn   = (const float*)d_in[4];
    const float* Ws   = (const float*)d_in[5];
    const float* bias = (const float*)d_in[6];
    float* out = (float*)d_out;

    const int n = in_sizes[0] / D;
    const int E = in_sizes[3];
    const int blk = 256;
    const int nb = ((n + 1) + SCHUNK - 1) / SCHUNK;

    histscan_kernel<<<nb, blk>>>(dst, n, E);
    {
        int nt = (E + 1) / 2;
        scatter_kernel<<<(nt + blk - 1) / blk, blk>>>(src, dst, w, E);
    }
    {
        int warps_per_blk = blk / 32;
        int grid = (n + warps_per_blk - 1) / warps_per_blk;
        agg_kernel<<<grid, blk>>>(x, n);
    }
    {
        size_t smem = (2ull * 128 * 128 + 2ull * 128 * RSTR) * sizeof(float); // 200,704 B
        cudaFuncSetAttribute(dual_gemm_kernel,
                             cudaFuncAttributeMaxDynamicSharedMemorySize,
                             (int)smem);
        int grid = (n + BM - 1) / BM;
        dual_gemm_kernel<<<grid, 256, smem>>>(x, Wn, Ws, bias, out, n);
    }
}

// round 14
// speedup vs baseline: 1.4439x; 1.4439x over previous
#include <cuda_runtime.h>
#include <cstdint>
#include <cstddef>

#define D 128
#define MAXN 100000
#define MAXE 1600000
#define SCHUNK 1024
#define NBLK_SCAN 98

// GEMM tile config
#define GBM 128          // rows per block
#define GBK 16           // k-slice
#define ASTR 132         // s_a row stride (floats), 16B-aligned, conflict-mild

typedef unsigned long long u64;

// ---------------------------------------------------------------------------
// Device scratch (static; allocation-guard-safe). Zero at load; g_cnt
// re-zeroed by histscan each launch; g_bar monotonic.
// ---------------------------------------------------------------------------
__device__ float g_agg[(size_t)MAXN * D];
__device__ u64   g_edges[MAXE];
__device__ int   g_cnt[MAXN];
__device__ int   g_row[MAXN + 1];
__device__ int   g_cur[MAXN];
__device__ int   g_look[NBLK_SCAN];
__device__ unsigned g_bar;

// ---------------------------------------------------------------------------
// f32x2 helpers
// ---------------------------------------------------------------------------
__device__ __forceinline__ u64 dup2(float f) {
    u64 r; unsigned u = __float_as_uint(f);
    asm("mov.b64 %0, {%1, %1};" : "=l"(r) : "r"(u));
    return r;
}
__device__ __forceinline__ void ffma2(u64& d, u64 a, u64 b) {
    asm("fma.rn.f32x2 %0, %1, %2, %0;" : "+l"(d) : "l"(a), "l"(b));
}
__device__ __forceinline__ u64 add2(u64 a, u64 b) {
    u64 r;
    asm("add.rn.f32x2 %0, %1, %2;" : "=l"(r) : "l"(a), "l"(b));
    return r;
}

__device__ __forceinline__ bool block_sniff64(const int* p, int* s_flag) {
    if (threadIdx.x == 0) {
        unsigned o = 0;
        #pragma unroll
        for (int j = 0; j < 16; j++) o |= (unsigned)p[2 * j + 1];
        *s_flag = (o == 0u) ? 1 : 0;
    }
    __syncthreads();
    return *s_flag != 0;
}

__device__ __forceinline__ void grid_barrier(int nb) {
    __syncthreads();
    if (threadIdx.x == 0) {
        __threadfence();
        unsigned my = atomicAdd(&g_bar, 1u);
        unsigned target = (my / nb + 1u) * (unsigned)nb;
        unsigned cur;
        do {
            asm volatile("ld.acquire.gpu.global.u32 %0, [%1];"
                         : "=r"(cur) : "l"(&g_bar) : "memory");
        } while (cur < target);
    }
    __syncthreads();
}

// ---------------------------------------------------------------------------
// Launch 1: histogram + scan (98 co-resident blocks, 2 grid barriers)
// ---------------------------------------------------------------------------
__global__ void __launch_bounds__(256) histscan_kernel(const int* __restrict__ dst_raw,
                                                       int n, int E) {
    __shared__ int s_is64;
    __shared__ int wsum[8];
    __shared__ int s_red[256];
    __shared__ int s_prefix;

    const int tid  = threadIdx.x;
    const int lane = tid & 31;
    const int wid  = tid >> 5;
    const int b    = blockIdx.x;
    const int nb   = gridDim.x;

    const bool is64 = block_sniff64(dst_raw, &s_is64);
    if (is64) {
        const long long* d64 = (const long long*)dst_raw;
        for (int e = b * 256 + tid; e < E; e += nb * 256)
            atomicAdd(&g_cnt[(int)d64[e]], 1);
    } else {
        for (int e = b * 256 + tid; e < E; e += nb * 256)
            atomicAdd(&g_cnt[dst_raw[e]], 1);
    }
    grid_barrier(nb);

    const int base = b * SCHUNK + tid * 4;
    int v[4];
    #pragma unroll
    for (int j = 0; j < 4; j++)
        v[j] = (base + j < n) ? g_cnt[base + j] : 0;
    int s = v[0] + v[1] + v[2] + v[3];

    int inc = s;
    #pragma unroll
    for (int off = 1; off < 32; off <<= 1) {
        int t = __shfl_up_sync(0xffffffffu, inc, off);
        if (lane >= off) inc += t;
    }
    if (lane == 31) wsum[wid] = inc;
    __syncthreads();
    if (wid == 0) {
        int wv = (lane < 8) ? wsum[lane] : 0;
        #pragma unroll
        for (int off = 1; off < 8; off <<= 1) {
            int t = __shfl_up_sync(0xffffffffu, wv, off);
            if (lane >= off) wv += t;
        }
        if (lane < 8) wsum[lane] = wv;
    }
    __syncthreads();
    if (tid == 0) g_look[b] = wsum[7];
    grid_barrier(nb);

    s_red[tid] = (tid < b) ? g_look[tid] : 0;
    __syncthreads();
    for (int off = 128; off > 0; off >>= 1) {
        if (tid < off) s_red[tid] += s_red[tid + off];
        __syncthreads();
    }
    if (tid == 0) s_prefix = s_red[0];
    __syncthreads();

    int excl = inc - s + (wid > 0 ? wsum[wid - 1] : 0) + s_prefix;
    #pragma unroll
    for (int j = 0; j < 4; j++) {
        int idx = base + j;
        if (idx <= n) {
            g_row[idx] = excl;
            if (idx < n) { g_cur[idx] = excl; g_cnt[idx] = 0; }
        }
        excl += v[j];
    }
}

// ---------------------------------------------------------------------------
// Launch 2: scatter packed (w,src) into CSR order
// ---------------------------------------------------------------------------
__global__ void __launch_bounds__(256) scatter_kernel(const int* __restrict__ src_raw,
                                                      const int* __restrict__ dst_raw,
                                                      const float* __restrict__ w, int E) {
    __shared__ int s_is64;
    const bool is64 = block_sniff64(dst_raw, &s_is64);
    int t = blockIdx.x * blockDim.x + threadIdx.x;
    int e = t * 2;
    if (e >= E) return;
    int cnt = min(2, E - e);
    #pragma unroll
    for (int j = 0; j < 2; j++) {
        if (j >= cnt) break;
        int s, d;
        if (is64) {
            s = (int)((const long long*)src_raw)[e + j];
            d = (int)((const long long*)dst_raw)[e + j];
        } else {
            s = src_raw[e + j];
            d = dst_raw[e + j];
        }
        float ww = w[e + j];
        int pos = atomicAdd(&g_cur[d], 1);
        g_edges[pos] = ((u64)__float_as_uint(ww) << 32) | (unsigned)s;
    }
}

// ---------------------------------------------------------------------------
// Launch 3: aggregation (unchanged — known 81 us)
// ---------------------------------------------------------------------------
__global__ void __launch_bounds__(256) agg_kernel(const float* __restrict__ x, int n) {
    const int warp = (blockIdx.x * blockDim.x + threadIdx.x) >> 5;
    if (warp >= n) return;
    const int lane = threadIdx.x & 31;

    const int beg = g_row[warp];
    const int end = g_row[warp + 1];
    const float4* x4 = (const float4*)x;

    float4 a0 = make_float4(0.f, 0.f, 0.f, 0.f);
    float4 a1 = make_float4(0.f, 0.f, 0.f, 0.f);
    float4 a2 = make_float4(0.f, 0.f, 0.f, 0.f);
    float4 a3 = make_float4(0.f, 0.f, 0.f, 0.f);

    int i = beg;
    for (; i + 3 < end; i += 4) {
        u64 e0 = g_edges[i];
        u64 e1 = g_edges[i + 1];
        u64 e2 = g_edges[i + 2];
        u64 e3 = g_edges[i + 3];
        float4 v0 = __ldg(&x4[(size_t)(unsigned)e0 * (D / 4) + lane]);
        float4 v1 = __ldg(&x4[(size_t)(unsigned)e1 * (D / 4) + lane]);
        float4 v2 = __ldg(&x4[(size_t)(unsigned)e2 * (D / 4) + lane]);
        float4 v3 = __ldg(&x4[(size_t)(unsigned)e3 * (D / 4) + lane]);
        float w0 = __uint_as_float((unsigned)(e0 >> 32));
        float w1 = __uint_as_float((unsigned)(e1 >> 32));
        float w2 = __uint_as_float((unsigned)(e2 >> 32));
        float w3 = __uint_as_float((unsigned)(e3 >> 32));
        a0.x += w0 * v0.x; a0.y += w0 * v0.y; a0.z += w0 * v0.z; a0.w += w0 * v0.w;
        a1.x += w1 * v1.x; a1.y += w1 * v1.y; a1.z += w1 * v1.z; a1.w += w1 * v1.w;
        a2.x += w2 * v2.x; a2.y += w2 * v2.y; a2.z += w2 * v2.z; a2.w += w2 * v2.w;
        a3.x += w3 * v3.x; a3.y += w3 * v3.y; a3.z += w3 * v3.z; a3.w += w3 * v3.w;
    }
    for (; i < end; i++) {
        u64 e0 = g_edges[i];
        float w0 = __uint_as_float((unsigned)(e0 >> 32));
        float4 v0 = __ldg(&x4[(size_t)(unsigned)e0 * (D / 4) + lane]);
        a0.x += w0 * v0.x; a0.y += w0 * v0.y; a0.z += w0 * v0.z; a0.w += w0 * v0.w;
    }
    float4 r;
    r.x = (a0.x + a1.x) + (a2.x + a3.x);
    r.y = (a0.y + a1.y) + (a2.y + a3.y);
    r.z = (a0.z + a1.z) + (a2.z + a3.z);
    r.w = (a0.w + a1.w) + (a2.w + a3.w);
    ((float4*)g_agg)[(size_t)warp * (D / 4) + lane] = r;
}

// ---------------------------------------------------------------------------
// Launch 4 (PROFILED SLOT): dual GEMM as ONE K=256 streaming SGEMM.
//   out = [agg | x] @ [Wn ; Ws] + bias
//   Block tile 128x128, bk=16, 256 threads, 8x8 per thread (32 f32x2 accs).
//   Smem 16.6 KB -> 2 blocks/SM (16 warps). Register-prefetch pipeline.
// ---------------------------------------------------------------------------
__global__ void __launch_bounds__(256, 2) dual_gemm_kernel(
    const float* __restrict__ x,
    const float* __restrict__ Wn,
    const float* __restrict__ Ws,
    const float* __restrict__ bias,
    float* __restrict__ out, int n)
{
    __shared__ float s_a[GBK][ASTR];   // [k][row] transposed A slice
    __shared__ float s_b[GBK][D];      // [k][col] B slice

    const int tid  = threadIdx.x;
    const int row0 = blockIdx.x * GBM;

    // thread tile mapping
    const int wid  = tid >> 5;
    const int lane = tid & 31;
    const int wc   = wid & 1;                 // 2 warp-cols x 64
    const int wr   = wid >> 1;                // 4 warp-rows x 32
    const int lr   = lane >> 3;               // 4 x 8-row groups
    const int lc   = lane & 7;                // 8 x 8-col groups
    const int tr0  = wr * 32 + lr * 8;        // thread rows tr0..tr0+7
    const int tc0  = wc * 64 + lc * 8;        // thread cols tc0..tc0+7

    // A-load mapping: idx = it*256+tid ; r = idx>>2 (0..127), k4 = idx&3
    const int ar0 = tid >> 2;
    const int ak4 = (tid & 3) * 4;
    // B-load mapping: r = idx>>5 (0..15), c4 = idx&31
    const int br0 = tid >> 5;
    const int bc4 = (tid & 31) * 4;

    float4 pa[2], pb[2];

    // ---- prefetch chunk 0
    {
        const float* As = g_agg;  // kbase=0 < 128
        const float* Bs = Wn;
        #pragma unroll
        for (int it = 0; it < 2; it++) {
            int r = ar0 + it * 64;
            int gr = row0 + r;
            pa[it] = (gr < n) ? *(const float4*)(As + (size_t)gr * D + ak4)
                              : make_float4(0.f, 0.f, 0.f, 0.f);
            int kr = br0 + it * 8;
            pb[it] = *(const float4*)(Bs + (size_t)kr * D + bc4);
        }
    }

    u64 acc[8][4];
    #pragma unroll
    for (int r = 0; r < 8; r++)
        #pragma unroll
        for (int c = 0; c < 4; c++) acc[r][c] = 0ull;

    const int NCHUNK = 256 / GBK;   // 16
    for (int ch = 0; ch < NCHUNK; ch++) {
        // store prefetched regs to smem
        __syncthreads();
        #pragma unroll
        for (int it = 0; it < 2; it++) {
            int r = ar0 + it * 64;
            s_a[ak4 + 0][r] = pa[it].x;
            s_a[ak4 + 1][r] = pa[it].y;
            s_a[ak4 + 2][r] = pa[it].z;
            s_a[ak4 + 3][r] = pa[it].w;
            int kr = br0 + it * 8;
            *(float4*)(&s_b[kr][bc4]) = pb[it];
        }
        __syncthreads();

        // prefetch next chunk
        if (ch + 1 < NCHUNK) {
            int kbase = (ch + 1) * GBK;
            const float* As = (kbase < 128) ? g_agg : x;
            const float* Bs = (kbase < 128) ? Wn : Ws;
            int ks = kbase & 127;
            #pragma unroll
            for (int it = 0; it < 2; it++) {
                int r = ar0 + it * 64;
                int gr = row0 + r;
                pa[it] = (gr < n) ? *(const float4*)(As + (size_t)gr * D + ks + ak4)
                                  : make_float4(0.f, 0.f, 0.f, 0.f);
                int kr = br0 + it * 8;
                pb[it] = *(const float4*)(Bs + (size_t)(ks + kr) * D + bc4);
            }
        }

        // compute on current slice
        #pragma unroll
        for (int k = 0; k < GBK; k++) {
            float4 a0 = *(const float4*)(&s_a[k][tr0]);
            float4 a1 = *(const float4*)(&s_a[k][tr0 + 4]);
            ulonglong2 b0 = *(const ulonglong2*)(&s_b[k][tc0]);      // cols 0-3
            ulonglong2 b1 = *(const ulonglong2*)(&s_b[k][tc0 + 4]);  // cols 4-7
            u64 A[8];
            A[0] = dup2(a0.x); A[1] = dup2(a0.y); A[2] = dup2(a0.z); A[3] = dup2(a0.w);
            A[4] = dup2(a1.x); A[5] = dup2(a1.y); A[6] = dup2(a1.z); A[7] = dup2(a1.w);
            #pragma unroll
            for (int r = 0; r < 8; r++) {
                ffma2(acc[r][0], A[r], b0.x);
                ffma2(acc[r][1], A[r], b0.y);
                ffma2(acc[r][2], A[r], b1.x);
                ffma2(acc[r][3], A[r], b1.y);
            }
        }
    }

    // epilogue: + bias, store
    u64 bb[4];
    #pragma unroll
    for (int c = 0; c < 4; c++) bb[c] = *(const u64*)(bias + tc0 + 2 * c);

    #pragma unroll
    for (int r = 0; r < 8; r++) {
        int row = row0 + tr0 + r;
        if (row >= n) continue;
        float* op = out + (size_t)row * D + tc0;
        ulonglong2 st0, st1;
        st0.x = add2(acc[r][0], bb[0]);
        st0.y = add2(acc[r][1], bb[1]);
        st1.x = add2(acc[r][2], bb[2]);
        st1.y = add2(acc[r][3], bb[3]);
        *(ulonglong2*)(op) = st0;
        *(ulonglong2*)(op + 4) = st1;
    }
}

// ---------------------------------------------------------------------------
// launch: histscan(1) scatter(2) agg(3) dual_gemm(4 = profiled slot)
// ---------------------------------------------------------------------------
extern "C" void kernel_launch(void* const* d_in, const int* in_sizes, int n_in,
                              void* d_out, int out_size) {
    const float* x    = (const float*)d_in[0];
    const int*   src  = (const int*)d_in[1];
    const int*   dst  = (const int*)d_in[2];
    const float* w    = (const float*)d_in[3];
    const float* Wn   = (const float*)d_in[4];
    const float* Ws   = (const float*)d_in[5];
    const float* bias = (const float*)d_in[6];
    float* out = (float*)d_out;

    const int n = in_sizes[0] / D;
    const int E = in_sizes[3];
    const int blk = 256;
    const int nb = ((n + 1) + SCHUNK - 1) / SCHUNK;

    histscan_kernel<<<nb, blk>>>(dst, n, E);
    {
        int nt = (E + 1) / 2;
        scatter_kernel<<<(nt + blk - 1) / blk, blk>>>(src, dst, w, E);
    }
    {
        int warps_per_blk = blk / 32;
        int grid = (n + warps_per_blk - 1) / warps_per_blk;
        agg_kernel<<<grid, blk>>>(x, n);
    }
    {
        int grid = (n + GBM - 1) / GBM;
        dual_gemm_kernel<<<grid, 256>>>(x, Wn, Ws, bias, out, n);
    }
}

// round 15
// speedup vs baseline: 1.5060x; 1.0430x over previous
#include <cuda_runtime.h>
#include <cstdint>
#include <cstddef>

#define D 128
#define MAXN 100000
#define MAXE 1600000
#define SCHUNK 1024
#define NBLK_SCAN 98

// GEMM tile config
#define GBM 128          // rows per block
#define GBK 16           // k-slice
#define ASTR 132         // s_a row stride (floats)

typedef unsigned long long u64;

// ---------------------------------------------------------------------------
// Device scratch (static; allocation-guard-safe)
// ---------------------------------------------------------------------------
__device__ float g_agg[(size_t)MAXN * D];
__device__ u64   g_edges[MAXE];
__device__ int   g_cnt[MAXN];
__device__ int   g_row[MAXN + 1];
__device__ int   g_cur[MAXN];
__device__ int   g_look[NBLK_SCAN];
__device__ unsigned g_bar;

// ---------------------------------------------------------------------------
// f32x2 helpers
// ---------------------------------------------------------------------------
__device__ __forceinline__ u64 dup2(float f) {
    u64 r; unsigned u = __float_as_uint(f);
    asm("mov.b64 %0, {%1, %1};" : "=l"(r) : "r"(u));
    return r;
}
__device__ __forceinline__ void ffma2(u64& d, u64 a, u64 b) {
    asm("fma.rn.f32x2 %0, %1, %2, %0;" : "+l"(d) : "l"(a), "l"(b));
}
__device__ __forceinline__ u64 add2(u64 a, u64 b) {
    u64 r;
    asm("add.rn.f32x2 %0, %1, %2;" : "=l"(r) : "l"(a), "l"(b));
    return r;
}

__device__ __forceinline__ bool block_sniff64(const int* p, int* s_flag) {
    if (threadIdx.x == 0) {
        unsigned o = 0;
        #pragma unroll
        for (int j = 0; j < 16; j++) o |= (unsigned)p[2 * j + 1];
        *s_flag = (o == 0u) ? 1 : 0;
    }
    __syncthreads();
    return *s_flag != 0;
}

__device__ __forceinline__ void grid_barrier(int nb) {
    __syncthreads();
    if (threadIdx.x == 0) {
        __threadfence();
        unsigned my = atomicAdd(&g_bar, 1u);
        unsigned target = (my / nb + 1u) * (unsigned)nb;
        unsigned cur;
        do {
            asm volatile("ld.acquire.gpu.global.u32 %0, [%1];"
                         : "=r"(cur) : "l"(&g_bar) : "memory");
        } while (cur < target);
    }
    __syncthreads();
}

// ---------------------------------------------------------------------------
// Launch 1: histogram + scan
// ---------------------------------------------------------------------------
__global__ void __launch_bounds__(256) histscan_kernel(const int* __restrict__ dst_raw,
                                                       int n, int E) {
    __shared__ int s_is64;
    __shared__ int wsum[8];
    __shared__ int s_red[256];
    __shared__ int s_prefix;

    const int tid  = threadIdx.x;
    const int lane = tid & 31;
    const int wid  = tid >> 5;
    const int b    = blockIdx.x;
    const int nb   = gridDim.x;

    const bool is64 = block_sniff64(dst_raw, &s_is64);
    if (is64) {
        const long long* d64 = (const long long*)dst_raw;
        for (int e = b * 256 + tid; e < E; e += nb * 256)
            atomicAdd(&g_cnt[(int)d64[e]], 1);
    } else {
        for (int e = b * 256 + tid; e < E; e += nb * 256)
            atomicAdd(&g_cnt[dst_raw[e]], 1);
    }
    grid_barrier(nb);

    const int base = b * SCHUNK + tid * 4;
    int v[4];
    #pragma unroll
    for (int j = 0; j < 4; j++)
        v[j] = (base + j < n) ? g_cnt[base + j] : 0;
    int s = v[0] + v[1] + v[2] + v[3];

    int inc = s;
    #pragma unroll
    for (int off = 1; off < 32; off <<= 1) {
        int t = __shfl_up_sync(0xffffffffu, inc, off);
        if (lane >= off) inc += t;
    }
    if (lane == 31) wsum[wid] = inc;
    __syncthreads();
    if (wid == 0) {
        int wv = (lane < 8) ? wsum[lane] : 0;
        #pragma unroll
        for (int off = 1; off < 8; off <<= 1) {
            int t = __shfl_up_sync(0xffffffffu, wv, off);
            if (lane >= off) wv += t;
        }
        if (lane < 8) wsum[lane] = wv;
    }
    __syncthreads();
    if (tid == 0) g_look[b] = wsum[7];
    grid_barrier(nb);

    s_red[tid] = (tid < b) ? g_look[tid] : 0;
    __syncthreads();
    for (int off = 128; off > 0; off >>= 1) {
        if (tid < off) s_red[tid] += s_red[tid + off];
        __syncthreads();
    }
    if (tid == 0) s_prefix = s_red[0];
    __syncthreads();

    int excl = inc - s + (wid > 0 ? wsum[wid - 1] : 0) + s_prefix;
    #pragma unroll
    for (int j = 0; j < 4; j++) {
        int idx = base + j;
        if (idx <= n) {
            g_row[idx] = excl;
            if (idx < n) { g_cur[idx] = excl; g_cnt[idx] = 0; }
        }
        excl += v[j];
    }
}

// ---------------------------------------------------------------------------
// Launch 2: scatter
// ---------------------------------------------------------------------------
__global__ void __launch_bounds__(256) scatter_kernel(const int* __restrict__ src_raw,
                                                      const int* __restrict__ dst_raw,
                                                      const float* __restrict__ w, int E) {
    __shared__ int s_is64;
    const bool is64 = block_sniff64(dst_raw, &s_is64);
    int t = blockIdx.x * blockDim.x + threadIdx.x;
    int e = t * 2;
    if (e >= E) return;
    int cnt = min(2, E - e);
    #pragma unroll
    for (int j = 0; j < 2; j++) {
        if (j >= cnt) break;
        int s, d;
        if (is64) {
            s = (int)((const long long*)src_raw)[e + j];
            d = (int)((const long long*)dst_raw)[e + j];
        } else {
            s = src_raw[e + j];
            d = dst_raw[e + j];
        }
        float ww = w[e + j];
        int pos = atomicAdd(&g_cur[d], 1);
        g_edges[pos] = ((u64)__float_as_uint(ww) << 32) | (unsigned)s;
    }
}

// ---------------------------------------------------------------------------
// Launch 3: aggregation (unchanged — known 81 us)
// ---------------------------------------------------------------------------
__global__ void __launch_bounds__(256) agg_kernel(const float* __restrict__ x, int n) {
    const int warp = (blockIdx.x * blockDim.x + threadIdx.x) >> 5;
    if (warp >= n) return;
    const int lane = threadIdx.x & 31;

    const int beg = g_row[warp];
    const int end = g_row[warp + 1];
    const float4* x4 = (const float4*)x;

    float4 a0 = make_float4(0.f, 0.f, 0.f, 0.f);
    float4 a1 = make_float4(0.f, 0.f, 0.f, 0.f);
    float4 a2 = make_float4(0.f, 0.f, 0.f, 0.f);
    float4 a3 = make_float4(0.f, 0.f, 0.f, 0.f);

    int i = beg;
    for (; i + 3 < end; i += 4) {
        u64 e0 = g_edges[i];
        u64 e1 = g_edges[i + 1];
        u64 e2 = g_edges[i + 2];
        u64 e3 = g_edges[i + 3];
        float4 v0 = __ldg(&x4[(size_t)(unsigned)e0 * (D / 4) + lane]);
        float4 v1 = __ldg(&x4[(size_t)(unsigned)e1 * (D / 4) + lane]);
        float4 v2 = __ldg(&x4[(size_t)(unsigned)e2 * (D / 4) + lane]);
        float4 v3 = __ldg(&x4[(size_t)(unsigned)e3 * (D / 4) + lane]);
        float w0 = __uint_as_float((unsigned)(e0 >> 32));
        float w1 = __uint_as_float((unsigned)(e1 >> 32));
        float w2 = __uint_as_float((unsigned)(e2 >> 32));
        float w3 = __uint_as_float((unsigned)(e3 >> 32));
        a0.x += w0 * v0.x; a0.y += w0 * v0.y; a0.z += w0 * v0.z; a0.w += w0 * v0.w;
        a1.x += w1 * v1.x; a1.y += w1 * v1.y; a1.z += w1 * v1.z; a1.w += w1 * v1.w;
        a2.x += w2 * v2.x; a2.y += w2 * v2.y; a2.z += w2 * v2.z; a2.w += w2 * v2.w;
        a3.x += w3 * v3.x; a3.y += w3 * v3.y; a3.z += w3 * v3.z; a3.w += w3 * v3.w;
    }
    for (; i < end; i++) {
        u64 e0 = g_edges[i];
        float w0 = __uint_as_float((unsigned)(e0 >> 32));
        float4 v0 = __ldg(&x4[(size_t)(unsigned)e0 * (D / 4) + lane]);
        a0.x += w0 * v0.x; a0.y += w0 * v0.y; a0.z += w0 * v0.z; a0.w += w0 * v0.w;
    }
    float4 r;
    r.x = (a0.x + a1.x) + (a2.x + a3.x);
    r.y = (a0.y + a1.y) + (a2.y + a3.y);
    r.z = (a0.z + a1.z) + (a2.z + a3.z);
    r.w = (a0.w + a1.w) + (a2.w + a3.w);
    ((float4*)g_agg)[(size_t)warp * (D / 4) + lane] = r;
}

// ---------------------------------------------------------------------------
// Launch 4 (PROFILED SLOT): K=256 streaming SGEMM, DOUBLE-BUFFERED smem.
//   out = [agg | x] @ [Wn ; Ws] + bias
//   128x128 block tile, bk=16, 256 threads, 8x8/thread, ONE sync per chunk.
// ---------------------------------------------------------------------------
__global__ void __launch_bounds__(256, 2) dual_gemm_kernel(
    const float* __restrict__ x,
    const float* __restrict__ Wn,
    const float* __restrict__ Ws,
    const float* __restrict__ bias,
    float* __restrict__ out, int n)
{
    __shared__ float s_a[2][GBK][ASTR];   // [buf][k][row]
    __shared__ float s_b[2][GBK][D];      // [buf][k][col]

    const int tid  = threadIdx.x;
    const int row0 = blockIdx.x * GBM;

    const int wid  = tid >> 5;
    const int lane = tid & 31;
    const int wc   = wid & 1;
    const int wr   = wid >> 1;
    const int lr   = lane >> 3;
    const int lc   = lane & 7;
    const int tr0  = wr * 32 + lr * 8;
    const int tc0  = wc * 64 + lc * 8;

    const int ar0 = tid >> 2;
    const int ak4 = (tid & 3) * 4;
    const int br0 = tid >> 5;
    const int bc4 = (tid & 31) * 4;

    float4 pa[2], pb[2];

    // prefetch chunk 0 and store to buffer 0
    {
        #pragma unroll
        for (int it = 0; it < 2; it++) {
            int r = ar0 + it * 64;
            int gr = row0 + r;
            pa[it] = (gr < n) ? *(const float4*)(g_agg + (size_t)gr * D + ak4)
                              : make_float4(0.f, 0.f, 0.f, 0.f);
            int kr = br0 + it * 8;
            pb[it] = *(const float4*)(Wn + (size_t)kr * D + bc4);
        }
        #pragma unroll
        for (int it = 0; it < 2; it++) {
            int r = ar0 + it * 64;
            s_a[0][ak4 + 0][r] = pa[it].x;
            s_a[0][ak4 + 1][r] = pa[it].y;
            s_a[0][ak4 + 2][r] = pa[it].z;
            s_a[0][ak4 + 3][r] = pa[it].w;
            int kr = br0 + it * 8;
            *(float4*)(&s_b[0][kr][bc4]) = pb[it];
        }
    }
    __syncthreads();

    u64 acc[8][4];
    #pragma unroll
    for (int r = 0; r < 8; r++)
        #pragma unroll
        for (int c = 0; c < 4; c++) acc[r][c] = 0ull;

    const int NCHUNK = 256 / GBK;   // 16
    int cur = 0;
    for (int ch = 0; ch < NCHUNK; ch++) {
        // prefetch next chunk gmem -> regs (overlaps compute below)
        if (ch + 1 < NCHUNK) {
            int kbase = (ch + 1) * GBK;
            const float* As = (kbase < 128) ? g_agg : x;
            const float* Bs = (kbase < 128) ? Wn : Ws;
            int ks = kbase & 127;
            #pragma unroll
            for (int it = 0; it < 2; it++) {
                int r = ar0 + it * 64;
                int gr = row0 + r;
                pa[it] = (gr < n) ? *(const float4*)(As + (size_t)gr * D + ks + ak4)
                                  : make_float4(0.f, 0.f, 0.f, 0.f);
                int kr = br0 + it * 8;
                pb[it] = *(const float4*)(Bs + (size_t)(ks + kr) * D + bc4);
            }
        }

        // compute on current buffer
        #pragma unroll
        for (int k = 0; k < GBK; k++) {
            float4 a0 = *(const float4*)(&s_a[cur][k][tr0]);
            float4 a1 = *(const float4*)(&s_a[cur][k][tr0 + 4]);
            ulonglong2 b0 = *(const ulonglong2*)(&s_b[cur][k][tc0]);
            ulonglong2 b1 = *(const ulonglong2*)(&s_b[cur][k][tc0 + 4]);
            u64 A[8];
            A[0] = dup2(a0.x); A[1] = dup2(a0.y); A[2] = dup2(a0.z); A[3] = dup2(a0.w);
            A[4] = dup2(a1.x); A[5] = dup2(a1.y); A[6] = dup2(a1.z); A[7] = dup2(a1.w);
            #pragma unroll
            for (int r = 0; r < 8; r++) {
                ffma2(acc[r][0], A[r], b0.x);
                ffma2(acc[r][1], A[r], b0.y);
                ffma2(acc[r][2], A[r], b1.x);
                ffma2(acc[r][3], A[r], b1.y);
            }
        }

        // store next chunk into the other buffer; one sync per chunk
        if (ch + 1 < NCHUNK) {
            int nxt = cur ^ 1;
            #pragma unroll
            for (int it = 0; it < 2; it++) {
                int r = ar0 + it * 64;
                s_a[nxt][ak4 + 0][r] = pa[it].x;
                s_a[nxt][ak4 + 1][r] = pa[it].y;
                s_a[nxt][ak4 + 2][r] = pa[it].z;
                s_a[nxt][ak4 + 3][r] = pa[it].w;
                int kr = br0 + it * 8;
                *(float4*)(&s_b[nxt][kr][bc4]) = pb[it];
            }
            __syncthreads();
            cur = nxt;
        }
    }

    // epilogue
    u64 bb[4];
    #pragma unroll
    for (int c = 0; c < 4; c++) bb[c] = *(const u64*)(bias + tc0 + 2 * c);

    #pragma unroll
    for (int r = 0; r < 8; r++) {
        int row = row0 + tr0 + r;
        if (row >= n) continue;
        float* op = out + (size_t)row * D + tc0;
        ulonglong2 st0, st1;
        st0.x = add2(acc[r][0], bb[0]);
        st0.y = add2(acc[r][1], bb[1]);
        st1.x = add2(acc[r][2], bb[2]);
        st1.y = add2(acc[r][3], bb[3]);
        *(ulonglong2*)(op) = st0;
        *(ulonglong2*)(op + 4) = st1;
    }
}

// ---------------------------------------------------------------------------
// launch: histscan(1) scatter(2) agg(3) dual_gemm(4 = profiled slot)
// ---------------------------------------------------------------------------
extern "C" void kernel_launch(void* const* d_in, const int* in_sizes, int n_in,
                              void* d_out, int out_size) {
    const float* x    = (const float*)d_in[0];
    const int*   src  = (const int*)d_in[1];
    const int*   dst  = (const int*)d_in[2];
    const float* w    = (const float*)d_in[3];
    const float* Wn   = (const float*)d_in[4];
    const float* Ws   = (const float*)d_in[5];
    const float* bias = (const float*)d_in[6];
    float* out = (float*)d_out;

    const int n = in_sizes[0] / D;
    const int E = in_sizes[3];
    const int blk = 256;
    const int nb = ((n + 1) + SCHUNK - 1) / SCHUNK;

    histscan_kernel<<<nb, blk>>>(dst, n, E);
    {
        int nt = (E + 1) / 2;
        scatter_kernel<<<(nt + blk - 1) / blk, blk>>>(src, dst, w, E);
    }
    {
        int warps_per_blk = blk / 32;
        int grid = (n + warps_per_blk - 1) / warps_per_blk;
        agg_kernel<<<grid, blk>>>(x, n);
    }
    {
        int grid = (n + GBM - 1) / GBM;
        dual_gemm_kernel<<<grid, 256>>>(x, Wn, Ws, bias, out, n);
    }
}

// round 16
// speedup vs baseline: 1.6888x; 1.1214x over previous
#include <cuda_runtime.h>
#include <cstdint>
#include <cstddef>

#define D 128
#define MAXN 100000
#define MAXE 1600000
#define SCHUNK 1024
#define NBLK_SCAN 98

// GEMM tile config
#define GBM 128          // rows per block tile
#define GBK 16           // k-slice
#define TSTR 132         // smem row stride (floats): banks (4c+g) conflict-free
#define BUFF (3 * GBK * TSTR)   // floats per buffer (ahi, alo, braw)

typedef unsigned long long u64;

// ---------------------------------------------------------------------------
// Device scratch (static; allocation-guard-safe)
// ---------------------------------------------------------------------------
__device__ float g_agg[(size_t)MAXN * D];
__device__ u64   g_edges[MAXE];
__device__ int   g_cnt[MAXN];
__device__ int   g_row[MAXN + 1];
__device__ int   g_cur[MAXN];
__device__ int   g_look[NBLK_SCAN];
__device__ unsigned g_bar;

// ---------------------------------------------------------------------------
// helpers
// ---------------------------------------------------------------------------
__device__ __forceinline__ float tf32r(float v) {
    unsigned u;
    asm("cvt.rna.tf32.f32 %0, %1;" : "=r"(u) : "f"(v));
    return __uint_as_float(u);
}

__device__ __forceinline__ void mma_tf32(float d[4],
                                         unsigned a0, unsigned a1, unsigned a2, unsigned a3,
                                         unsigned b0, unsigned b1) {
    asm volatile(
        "mma.sync.aligned.m16n8k8.row.col.f32.tf32.tf32.f32 "
        "{%0,%1,%2,%3}, {%4,%5,%6,%7}, {%8,%9}, {%0,%1,%2,%3};\n"
        : "+f"(d[0]), "+f"(d[1]), "+f"(d[2]), "+f"(d[3])
        : "r"(a0), "r"(a1), "r"(a2), "r"(a3), "r"(b0), "r"(b1));
}

__device__ __forceinline__ bool block_sniff64(const int* p, int* s_flag) {
    if (threadIdx.x == 0) {
        unsigned o = 0;
        #pragma unroll
        for (int j = 0; j < 16; j++) o |= (unsigned)p[2 * j + 1];
        *s_flag = (o == 0u) ? 1 : 0;
    }
    __syncthreads();
    return *s_flag != 0;
}

__device__ __forceinline__ void grid_barrier(int nb) {
    __syncthreads();
    if (threadIdx.x == 0) {
        __threadfence();
        unsigned my = atomicAdd(&g_bar, 1u);
        unsigned target = (my / nb + 1u) * (unsigned)nb;
        unsigned cur;
        do {
            asm volatile("ld.acquire.gpu.global.u32 %0, [%1];"
                         : "=r"(cur) : "l"(&g_bar) : "memory");
        } while (cur < target);
    }
    __syncthreads();
}

// ---------------------------------------------------------------------------
// Launch 1: histogram + scan (unchanged)
// ---------------------------------------------------------------------------
__global__ void __launch_bounds__(256) histscan_kernel(const int* __restrict__ dst_raw,
                                                       int n, int E) {
    __shared__ int s_is64;
    __shared__ int wsum[8];
    __shared__ int s_red[256];
    __shared__ int s_prefix;

    const int tid  = threadIdx.x;
    const int lane = tid & 31;
    const int wid  = tid >> 5;
    const int b    = blockIdx.x;
    const int nb   = gridDim.x;

    const bool is64 = block_sniff64(dst_raw, &s_is64);
    if (is64) {
        const long long* d64 = (const long long*)dst_raw;
        for (int e = b * 256 + tid; e < E; e += nb * 256)
            atomicAdd(&g_cnt[(int)d64[e]], 1);
    } else {
        for (int e = b * 256 + tid; e < E; e += nb * 256)
            atomicAdd(&g_cnt[dst_raw[e]], 1);
    }
    grid_barrier(nb);

    const int base = b * SCHUNK + tid * 4;
    int v[4];
    #pragma unroll
    for (int j = 0; j < 4; j++)
        v[j] = (base + j < n) ? g_cnt[base + j] : 0;
    int s = v[0] + v[1] + v[2] + v[3];

    int inc = s;
    #pragma unroll
    for (int off = 1; off < 32; off <<= 1) {
        int t = __shfl_up_sync(0xffffffffu, inc, off);
        if (lane >= off) inc += t;
    }
    if (lane == 31) wsum[wid] = inc;
    __syncthreads();
    if (wid == 0) {
        int wv = (lane < 8) ? wsum[lane] : 0;
        #pragma unroll
        for (int off = 1; off < 8; off <<= 1) {
            int t = __shfl_up_sync(0xffffffffu, wv, off);
            if (lane >= off) wv += t;
        }
        if (lane < 8) wsum[lane] = wv;
    }
    __syncthreads();
    if (tid == 0) g_look[b] = wsum[7];
    grid_barrier(nb);

    s_red[tid] = (tid < b) ? g_look[tid] : 0;
    __syncthreads();
    for (int off = 128; off > 0; off >>= 1) {
        if (tid < off) s_red[tid] += s_red[tid + off];
        __syncthreads();
    }
    if (tid == 0) s_prefix = s_red[0];
    __syncthreads();

    int excl = inc - s + (wid > 0 ? wsum[wid - 1] : 0) + s_prefix;
    #pragma unroll
    for (int j = 0; j < 4; j++) {
        int idx = base + j;
        if (idx <= n) {
            g_row[idx] = excl;
            if (idx < n) { g_cur[idx] = excl; g_cnt[idx] = 0; }
        }
        excl += v[j];
    }
}

// ---------------------------------------------------------------------------
// Launch 2: scatter (unchanged)
// ---------------------------------------------------------------------------
__global__ void __launch_bounds__(256) scatter_kernel(const int* __restrict__ src_raw,
                                                      const int* __restrict__ dst_raw,
                                                      const float* __restrict__ w, int E) {
    __shared__ int s_is64;
    const bool is64 = block_sniff64(dst_raw, &s_is64);
    int t = blockIdx.x * blockDim.x + threadIdx.x;
    int e = t * 2;
    if (e >= E) return;
    int cnt = min(2, E - e);
    #pragma unroll
    for (int j = 0; j < 2; j++) {
        if (j >= cnt) break;
        int s, d;
        if (is64) {
            s = (int)((const long long*)src_raw)[e + j];
            d = (int)((const long long*)dst_raw)[e + j];
        } else {
            s = src_raw[e + j];
            d = dst_raw[e + j];
        }
        float ww = w[e + j];
        int pos = atomicAdd(&g_cur[d], 1);
        g_edges[pos] = ((u64)__float_as_uint(ww) << 32) | (unsigned)s;
    }
}

// ---------------------------------------------------------------------------
// Launch 3: aggregation (unchanged — known 81 us)
// ---------------------------------------------------------------------------
__global__ void __launch_bounds__(256) agg_kernel(const float* __restrict__ x, int n) {
    const int warp = (blockIdx.x * blockDim.x + threadIdx.x) >> 5;
    if (warp >= n) return;
    const int lane = threadIdx.x & 31;

    const int beg = g_row[warp];
    const int end = g_row[warp + 1];
    const float4* x4 = (const float4*)x;

    float4 a0 = make_float4(0.f, 0.f, 0.f, 0.f);
    float4 a1 = make_float4(0.f, 0.f, 0.f, 0.f);
    float4 a2 = make_float4(0.f, 0.f, 0.f, 0.f);
    float4 a3 = make_float4(0.f, 0.f, 0.f, 0.f);

    int i = beg;
    for (; i + 3 < end; i += 4) {
        u64 e0 = g_edges[i];
        u64 e1 = g_edges[i + 1];
        u64 e2 = g_edges[i + 2];
        u64 e3 = g_edges[i + 3];
        float4 v0 = __ldg(&x4[(size_t)(unsigned)e0 * (D / 4) + lane]);
        float4 v1 = __ldg(&x4[(size_t)(unsigned)e1 * (D / 4) + lane]);
        float4 v2 = __ldg(&x4[(size_t)(unsigned)e2 * (D / 4) + lane]);
        float4 v3 = __ldg(&x4[(size_t)(unsigned)e3 * (D / 4) + lane]);
        float w0 = __uint_as_float((unsigned)(e0 >> 32));
        float w1 = __uint_as_float((unsigned)(e1 >> 32));
        float w2 = __uint_as_float((unsigned)(e2 >> 32));
        float w3 = __uint_as_float((unsigned)(e3 >> 32));
        a0.x += w0 * v0.x; a0.y += w0 * v0.y; a0.z += w0 * v0.z; a0.w += w0 * v0.w;
        a1.x += w1 * v1.x; a1.y += w1 * v1.y; a1.z += w1 * v1.z; a1.w += w1 * v1.w;
        a2.x += w2 * v2.x; a2.y += w2 * v2.y; a2.z += w2 * v2.z; a2.w += w2 * v2.w;
        a3.x += w3 * v3.x; a3.y += w3 * v3.y; a3.z += w3 * v3.z; a3.w += w3 * v3.w;
    }
    for (; i < end; i++) {
        u64 e0 = g_edges[i];
        float w0 = __uint_as_float((unsigned)(e0 >> 32));
        float4 v0 = __ldg(&x4[(size_t)(unsigned)e0 * (D / 4) + lane]);
        a0.x += w0 * v0.x; a0.y += w0 * v0.y; a0.z += w0 * v0.z; a0.w += w0 * v0.w;
    }
    float4 r;
    r.x = (a0.x + a1.x) + (a2.x + a3.x);
    r.y = (a0.y + a1.y) + (a2.y + a3.y);
    r.z = (a0.z + a1.z) + (a2.z + a3.z);
    r.w = (a0.w + a1.w) + (a2.w + a3.w);
    ((float4*)g_agg)[(size_t)warp * (D / 4) + lane] = r;
}

// ---------------------------------------------------------------------------
// Launch 4 (PROFILED SLOT): 3xTF32 tensor-core GEMM
//   out = [agg | x] @ [Wn ; Ws] + bias        (K = 256 streamed, bk = 16)
//   Block 128x128, 256 threads = 8 warps (4x2), warp tile 32x64
//   A split into (hi, lo) tf32 at smem store; B split in regs at frag load.
//   D += Ahi*Bhi + Ahi*Blo + Alo*Bhi  (error ~2^-22, fp32 accumulate)
// ---------------------------------------------------------------------------
__global__ void __launch_bounds__(256, 2) dual_gemm_kernel(
    const float* __restrict__ x,
    const float* __restrict__ Wn,
    const float* __restrict__ Ws,
    const float* __restrict__ bias,
    float* __restrict__ out, int n)
{
    extern __shared__ float sm[];
    // per buffer: [ahi 16x132][alo 16x132][braw 16x132]
    #define SAHI(buf, k, r) sm[(buf) * BUFF + (k) * TSTR + (r)]
    #define SALO(buf, k, r) sm[(buf) * BUFF + GBK * TSTR + (k) * TSTR + (r)]
    #define SBR(buf, k, c)  sm[(buf) * BUFF + 2 * GBK * TSTR + (k) * TSTR + (c)]

    const int tid  = threadIdx.x;
    const int row0 = blockIdx.x * GBM;

    const int wid  = tid >> 5;
    const int lane = tid & 31;
    const int wr   = wid >> 1;        // 4 warp rows x 32
    const int wc   = wid & 1;         // 2 warp cols x 64
    const int grp  = lane >> 2;       // 0..7
    const int tig  = lane & 3;        // 0..3

    // staging maps (as R15)
    const int ar0 = tid >> 2;          // 0..63 (+64)
    const int ak4 = (tid & 3) * 4;     // k group
    const int br0 = tid >> 5;          // 0..7 (+8)
    const int bc4 = (tid & 31) * 4;    // col group

    float4 pa[2], pb[2];

    // ---- prefetch chunk 0 + split-store into buffer 0
    {
        #pragma unroll
        for (int it = 0; it < 2; it++) {
            int r = ar0 + it * 64;
            int gr = row0 + r;
            pa[it] = (gr < n) ? *(const float4*)(g_agg + (size_t)gr * D + ak4)
                              : make_float4(0.f, 0.f, 0.f, 0.f);
            int kr = br0 + it * 8;
            pb[it] = *(const float4*)(Wn + (size_t)kr * D + bc4);
        }
        #pragma unroll
        for (int it = 0; it < 2; it++) {
            int r = ar0 + it * 64;
            float va[4] = {pa[it].x, pa[it].y, pa[it].z, pa[it].w};
            #pragma unroll
            for (int j = 0; j < 4; j++) {
                float hi = tf32r(va[j]);
                float lo = tf32r(va[j] - hi);
                SAHI(0, ak4 + j, r) = hi;
                SALO(0, ak4 + j, r) = lo;
            }
            int kr = br0 + it * 8;
            *(float4*)(&SBR(0, kr, bc4)) = pb[it];
        }
    }
    __syncthreads();

    float acc[2][8][4];
    #pragma unroll
    for (int mt = 0; mt < 2; mt++)
        #pragma unroll
        for (int nt = 0; nt < 8; nt++)
            #pragma unroll
            for (int c = 0; c < 4; c++) acc[mt][nt][c] = 0.f;

    const int NCHUNK = 256 / GBK;   // 16
    int cur = 0;
    for (int ch = 0; ch < NCHUNK; ch++) {
        // prefetch next chunk gmem -> regs
        if (ch + 1 < NCHUNK) {
            int kbase = (ch + 1) * GBK;
            const float* As = (kbase < 128) ? g_agg : x;
            const float* Bs = (kbase < 128) ? Wn : Ws;
            int ks = kbase & 127;
            #pragma unroll
            for (int it = 0; it < 2; it++) {
                int r = ar0 + it * 64;
                int gr = row0 + r;
                pa[it] = (gr < n) ? *(const float4*)(As + (size_t)gr * D + ks + ak4)
                                  : make_float4(0.f, 0.f, 0.f, 0.f);
                int kr = br0 + it * 8;
                pb[it] = *(const float4*)(Bs + (size_t)(ks + kr) * D + bc4);
            }
        }

        // compute: two k8 steps per chunk
        #pragma unroll
        for (int ks = 0; ks < GBK; ks += 8) {
            // A fragments (pre-split hi/lo from smem)
            unsigned ahi[2][4], alo[2][4];
            #pragma unroll
            for (int mt = 0; mt < 2; mt++) {
                int rb = wr * 32 + mt * 16;
                ahi[mt][0] = __float_as_uint(SAHI(cur, ks + tig,     rb + grp));
                ahi[mt][1] = __float_as_uint(SAHI(cur, ks + tig,     rb + grp + 8));
                ahi[mt][2] = __float_as_uint(SAHI(cur, ks + tig + 4, rb + grp));
                ahi[mt][3] = __float_as_uint(SAHI(cur, ks + tig + 4, rb + grp + 8));
                alo[mt][0] = __float_as_uint(SALO(cur, ks + tig,     rb + grp));
                alo[mt][1] = __float_as_uint(SALO(cur, ks + tig,     rb + grp + 8));
                alo[mt][2] = __float_as_uint(SALO(cur, ks + tig + 4, rb + grp));
                alo[mt][3] = __float_as_uint(SALO(cur, ks + tig + 4, rb + grp + 8));
            }
            // B fragments per n-tile: raw load + reg split
            #pragma unroll
            for (int nt = 0; nt < 8; nt++) {
                int cb = wc * 64 + nt * 8;
                float b0r = SBR(cur, ks + tig,     cb + grp);
                float b1r = SBR(cur, ks + tig + 4, cb + grp);
                float b0h = tf32r(b0r), b1h = tf32r(b1r);
                float b0l = tf32r(b0r - b0h), b1l = tf32r(b1r - b1h);
                unsigned bh0 = __float_as_uint(b0h), bh1 = __float_as_uint(b1h);
                unsigned bl0 = __float_as_uint(b0l), bl1 = __float_as_uint(b1l);
                #pragma unroll
                for (int mt = 0; mt < 2; mt++) {
                    mma_tf32(acc[mt][nt], ahi[mt][0], ahi[mt][1], ahi[mt][2], ahi[mt][3], bh0, bh1);
                    mma_tf32(acc[mt][nt], ahi[mt][0], ahi[mt][1], ahi[mt][2], ahi[mt][3], bl0, bl1);
                    mma_tf32(acc[mt][nt], alo[mt][0], alo[mt][1], alo[mt][2], alo[mt][3], bh0, bh1);
                }
            }
        }

        // split-store next chunk into other buffer; one sync per chunk
        if (ch + 1 < NCHUNK) {
            int nxt = cur ^ 1;
            #pragma unroll
            for (int it = 0; it < 2; it++) {
                int r = ar0 + it * 64;
                float va[4] = {pa[it].x, pa[it].y, pa[it].z, pa[it].w};
                #pragma unroll
                for (int j = 0; j < 4; j++) {
                    float hi = tf32r(va[j]);
                    float lo = tf32r(va[j] - hi);
                    SAHI(nxt, ak4 + j, r) = hi;
                    SALO(nxt, ak4 + j, r) = lo;
                }
                int kr = br0 + it * 8;
                *(float4*)(&SBR(nxt, kr, bc4)) = pb[it];
            }
            __syncthreads();
            cur = nxt;
        }
    }

    // epilogue: + bias, store (rows grp / grp+8, cols 2*tig,2*tig+1)
    #pragma unroll
    for (int mt = 0; mt < 2; mt++) {
        int rbase = row0 + wr * 32 + mt * 16;
        #pragma unroll
        for (int nt = 0; nt < 8; nt++) {
            int col = wc * 64 + nt * 8 + 2 * tig;
            float2 bv = *(const float2*)(bias + col);
            int r1 = rbase + grp;
            int r2 = r1 + 8;
            if (r1 < n) {
                float2 o;
                o.x = acc[mt][nt][0] + bv.x;
                o.y = acc[mt][nt][1] + bv.y;
                *(float2*)(out + (size_t)r1 * D + col) = o;
            }
            if (r2 < n) {
                float2 o;
                o.x = acc[mt][nt][2] + bv.x;
                o.y = acc[mt][nt][3] + bv.y;
                *(float2*)(out + (size_t)r2 * D + col) = o;
            }
        }
    }
    #undef SAHI
    #undef SALO
    #undef SBR
}

// ---------------------------------------------------------------------------
// launch: histscan(1) scatter(2) agg(3) dual_gemm(4 = profiled slot)
// ---------------------------------------------------------------------------
extern "C" void kernel_launch(void* const* d_in, const int* in_sizes, int n_in,
                              void* d_out, int out_size) {
    const float* x    = (const float*)d_in[0];
    const int*   src  = (const int*)d_in[1];
    const int*   dst  = (const int*)d_in[2];
    const float* w    = (const float*)d_in[3];
    const float* Wn   = (const float*)d_in[4];
    const float* Ws   = (const float*)d_in[5];
    const float* bias = (const float*)d_in[6];
    float* out = (float*)d_out;

    const int n = in_sizes[0] / D;
    const int E = in_sizes[3];
    const int blk = 256;
    const int nb = ((n + 1) + SCHUNK - 1) / SCHUNK;

    histscan_kernel<<<nb, blk>>>(dst, n, E);
    {
        int nt = (E + 1) / 2;
        scatter_kernel<<<(nt + blk - 1) / blk, blk>>>(src, dst, w, E);
    }
    {
        int warps_per_blk = blk / 32;
        int grid = (n + warps_per_blk - 1) / warps_per_blk;
        agg_kernel<<<grid, blk>>>(x, n);
    }
    {
        size_t smem = 2ull * BUFF * sizeof(float);   // 50,688 B
        cudaFuncSetAttribute(dual_gemm_kernel,
                             cudaFuncAttributeMaxDynamicSharedMemorySize,
                             (int)smem);
        int grid = (n + GBM - 1) / GBM;
        dual_gemm_kernel<<<grid, 256, smem>>>(x, Wn, Ws, bias, out, n);
    }
}